// round 1
// baseline (speedup 1.0000x reference)
#include <cuda_runtime.h>
#include <math.h>
#include <stdint.h>

// ---------------- problem constants ----------------
#define NMAX 200000
#define B_   4
#define C2D  128
#define H_   96
#define W_   312
#define MID  128
#define C3D  64

// ---------------- scratch (__device__ globals; no runtime alloc) ----------------
__device__ float g_imgT[(size_t)B_ * H_ * W_ * C2D];     // 61 MB  channel-last image
__device__ float g_hpre[(size_t)NMAX * MID];             // 102 MB pre-BN hidden
__device__ float g_vfeat[(size_t)NMAX * MID];            // 102 MB
__device__ float g_ifeat[(size_t)NMAX * C2D];            // 102 MB
__device__ float g_att[NMAX];                            // attention scalar a
__device__ float g_stats[512];   // [sum1(128) | sq1(128) | sumf(128) | sqf(128)]
__device__ float g_bnp[512];     // [scale1    | shift1   | scalef    | shiftf  ]

// ---------------- K-zero: clear stats ----------------
__global__ void k_zero() {
    if (threadIdx.x < 512) g_stats[threadIdx.x] = 0.f;
}

// ---------------- K0: image transpose [B,C,H,W] -> [B,H,W,C] ----------------
__global__ void k_transpose(const float* __restrict__ img) {
    __shared__ float tile[32][33];
    int bh = blockIdx.z;           // b*H + h
    int b  = bh / H_;
    int hh = bh % H_;
    int w0 = blockIdx.x * 32;
    int c0 = blockIdx.y * 32;
    int tx = threadIdx.x, ty = threadIdx.y;
    #pragma unroll
    for (int i = 0; i < 32; i += 8) {
        int c = c0 + ty + i;
        int w = w0 + tx;
        float v = 0.f;
        if (w < W_) v = img[((size_t)(b * C2D + c) * H_ + hh) * W_ + w];
        tile[ty + i][tx] = v;
    }
    __syncthreads();
    #pragma unroll
    for (int i = 0; i < 32; i += 8) {
        int w = w0 + ty + i;
        int c = c0 + tx;
        if (w < W_)
            g_imgT[((size_t)bh * W_ + w) * C2D + c] = tile[tx][ty + i];
    }
}

// ---------------- K1: hpre = vf @ w1^T + b1, accumulate bn1 stats ----------------
__global__ __launch_bounds__(128) void k_gemm1(const float* __restrict__ vf,
                                               const float* __restrict__ w1,
                                               const float* __restrict__ b1,
                                               int N) {
    int j = threadIdx.x;
    float w[C3D];
    const float4* wp = reinterpret_cast<const float4*>(w1 + (size_t)j * C3D);
    #pragma unroll
    for (int k = 0; k < C3D / 4; k++) {
        float4 v = __ldg(wp + k);
        w[4*k] = v.x; w[4*k+1] = v.y; w[4*k+2] = v.z; w[4*k+3] = v.w;
    }
    float bias = __ldg(b1 + j);
    __shared__ float sx[8][C3D];
    float ssum = 0.f, ssq = 0.f;
    int row0 = blockIdx.x * 128;
    for (int rt = 0; rt < 128; rt += 8) {
        int base = row0 + rt;
        {   // 8 rows x 64 floats = 128 float4 loads, one per thread
            int r = j >> 4, c = (j & 15) * 4;
            float4 v = make_float4(0.f, 0.f, 0.f, 0.f);
            if (base + r < N)
                v = *reinterpret_cast<const float4*>(vf + (size_t)(base + r) * C3D + c);
            sx[r][c] = v.x; sx[r][c+1] = v.y; sx[r][c+2] = v.z; sx[r][c+3] = v.w;
        }
        __syncthreads();
        #pragma unroll
        for (int r = 0; r < 8; r++) {
            if (base + r < N) {
                float a0 = 0.f, a1 = 0.f, a2 = 0.f, a3 = 0.f;
                const float4* xp = reinterpret_cast<const float4*>(&sx[r][0]);
                #pragma unroll
                for (int k = 0; k < C3D / 4; k++) {
                    float4 xv = xp[k];
                    a0 = fmaf(w[4*k],   xv.x, a0);
                    a1 = fmaf(w[4*k+1], xv.y, a1);
                    a2 = fmaf(w[4*k+2], xv.z, a2);
                    a3 = fmaf(w[4*k+3], xv.w, a3);
                }
                float acc = bias + ((a0 + a1) + (a2 + a3));
                g_hpre[(size_t)(base + r) * MID + j] = acc;
                ssum += acc; ssq += acc * acc;
            }
        }
        __syncthreads();
    }
    atomicAdd(&g_stats[j], ssum);
    atomicAdd(&g_stats[128 + j], ssq);
}

// ---------------- finalize batchnorm stats -> scale/shift ----------------
__global__ void k_fin(int which, const float* __restrict__ g,
                      const float* __restrict__ b, int N) {
    int j = threadIdx.x;   // 128 threads
    int o = which * 256;
    float invN = 1.f / (float)N;
    float m   = g_stats[o + j] * invN;
    float msq = g_stats[o + 128 + j] * invN;
    float var = msq - m * m;
    float s = __ldg(g + j) * rsqrtf(var + 1e-5f);
    g_bnp[o + j] = s;
    g_bnp[o + 128 + j] = __ldg(b + j) - m * s;
}

// ---------------- K3: vfeat = relu(bn(hpre)) @ w2^T + b2 ----------------
__global__ __launch_bounds__(128) void k_gemm2(const float* __restrict__ w2,
                                               const float* __restrict__ b2,
                                               int N) {
    int j = threadIdx.x;
    float w[MID];
    const float4* wp = reinterpret_cast<const float4*>(w2 + (size_t)j * MID);
    #pragma unroll
    for (int k = 0; k < MID / 4; k++) {
        float4 v = __ldg(wp + k);
        w[4*k] = v.x; w[4*k+1] = v.y; w[4*k+2] = v.z; w[4*k+3] = v.w;
    }
    float bias = __ldg(b2 + j);
    float sc = g_bnp[j], sh = g_bnp[128 + j];
    __shared__ float sx[4][MID];
    int row0 = blockIdx.x * 128;
    for (int rt = 0; rt < 128; rt += 4) {
        int base = row0 + rt;
        #pragma unroll
        for (int r = 0; r < 4; r++) {
            float v = 0.f;
            if (base + r < N) v = g_hpre[(size_t)(base + r) * MID + j];
            sx[r][j] = fmaxf(fmaf(v, sc, sh), 0.f);
        }
        __syncthreads();
        #pragma unroll
        for (int r = 0; r < 4; r++) {
            if (base + r < N) {
                float a0 = 0.f, a1 = 0.f, a2 = 0.f, a3 = 0.f;
                const float4* xp = reinterpret_cast<const float4*>(&sx[r][0]);
                #pragma unroll
                for (int k = 0; k < MID / 4; k++) {
                    float4 xv = xp[k];
                    a0 = fmaf(w[4*k],   xv.x, a0);
                    a1 = fmaf(w[4*k+1], xv.y, a1);
                    a2 = fmaf(w[4*k+2], xv.z, a2);
                    a3 = fmaf(w[4*k+3], xv.w, a3);
                }
                g_vfeat[(size_t)(base + r) * MID + j] = bias + ((a0 + a1) + (a2 + a3));
            }
        }
        __syncthreads();
    }
}

// ---------------- K4: projection + bilinear gather -> ifeat ----------------
__global__ __launch_bounds__(128) void k_sample(const int* __restrict__ coords,
                                                const float* __restrict__ P2,
                                                int N) {
    int j = threadIdx.x;
    int row0 = blockIdx.x * 64;
    int rend = N - row0; if (rend > 64) rend = 64;
    for (int r = 0; r < rend; r++) {
        int row = row0 + r;
        int4 c4 = __ldg(reinterpret_cast<const int4*>(coords + (size_t)row * 4));
        int b = c4.x;
        float p0 = (float)c4.y * 0.05f;
        float p1 = (float)c4.z * 0.05f - 40.f;
        float p2 = (float)c4.w * 0.1f  - 3.f;
        const float* P = P2 + b * 12;
        float cam0 = __ldg(P+0)*p0 + __ldg(P+1)*p1 + __ldg(P+2)*p2  + __ldg(P+3);
        float cam1 = __ldg(P+4)*p0 + __ldg(P+5)*p1 + __ldg(P+6)*p2  + __ldg(P+7);
        float cam2 = __ldg(P+8)*p0 + __ldg(P+9)*p1 + __ldg(P+10)*p2 + __ldg(P+11);
        float d = cam2 + 1e-8f;
        float u = cam0 / d;
        float v = cam1 / d;
        float gx = u / (float)W_ * 2.f - 1.f; gx = fminf(fmaxf(gx, -1.f), 1.f);
        float gy = v / (float)H_ * 2.f - 1.f; gy = fminf(fmaxf(gy, -1.f), 1.f);
        float ix = ((gx + 1.f) * (float)W_ - 1.f) * 0.5f;
        float iy = ((gy + 1.f) * (float)H_ - 1.f) * 0.5f;
        float x0f = floorf(ix), y0f = floorf(iy);
        float wx = ix - x0f, wy = iy - y0f;
        int x0 = (int)x0f, y0 = (int)y0f;
        float acc = 0.f;
        #pragma unroll
        for (int cy = 0; cy < 2; cy++) {
            #pragma unroll
            for (int cx = 0; cx < 2; cx++) {
                int yc = y0 + cy, xc = x0 + cx;
                float wgt = (cx ? wx : 1.f - wx) * (cy ? wy : 1.f - wy);
                if (xc >= 0 && xc < W_ && yc >= 0 && yc < H_) {
                    acc = fmaf(wgt,
                               g_imgT[(((size_t)(b * H_ + yc)) * W_ + xc) * C2D + j],
                               acc);
                }
            }
        }
        g_ifeat[(size_t)row * C2D + j] = acc;
    }
}

// ---------------- K5: attention scalar a per row ----------------
__global__ __launch_bounds__(256) void k_att(const float* __restrict__ aw1,
                                             const float* __restrict__ ab1,
                                             const float* __restrict__ aw2,
                                             const float* __restrict__ ab2,
                                             int N) {
    int t = threadIdx.x;
    int j = t >> 1, h = t & 1;
    float w[128];
    const float4* wp = reinterpret_cast<const float4*>(aw1 + (size_t)j * 256 + h * 128);
    #pragma unroll
    for (int k = 0; k < 32; k++) {
        float4 v = __ldg(wp + k);
        w[4*k] = v.x; w[4*k+1] = v.y; w[4*k+2] = v.z; w[4*k+3] = v.w;
    }
    float bj  = __ldg(ab1 + j);
    float w2j = __ldg(aw2 + j);
    float b2  = __ldg(ab2);
    __shared__ float sc[4][256];
    __shared__ float spart[8];
    int row0 = blockIdx.x * 64;
    for (int rt = 0; rt < 64; rt += 4) {
        int base = row0 + rt;
        #pragma unroll
        for (int it = 0; it < 4; it++) {
            int lin = t + it * 256;
            int r = lin >> 8, c = lin & 255;
            float v = 0.f;
            if (base + r < N)
                v = (c < 128) ? g_vfeat[(size_t)(base + r) * 128 + c]
                              : g_ifeat[(size_t)(base + r) * 128 + (c - 128)];
            sc[r][c] = v;
        }
        __syncthreads();
        for (int r = 0; r < 4; r++) {
            float a0 = 0.f, a1 = 0.f, a2 = 0.f, a3 = 0.f;
            const float4* xp = reinterpret_cast<const float4*>(&sc[r][0] + h * 128);
            #pragma unroll
            for (int k = 0; k < 32; k++) {
                float4 xv = xp[k];
                a0 = fmaf(w[4*k],   xv.x, a0);
                a1 = fmaf(w[4*k+1], xv.y, a1);
                a2 = fmaf(w[4*k+2], xv.z, a2);
                a3 = fmaf(w[4*k+3], xv.w, a3);
            }
            float acc = (a0 + a1) + (a2 + a3);
            acc += __shfl_xor_sync(0xffffffffu, acc, 1);
            float p = (h == 0) ? fmaxf(acc + bj, 0.f) * w2j : 0.f;
            #pragma unroll
            for (int o = 16; o > 0; o >>= 1) p += __shfl_xor_sync(0xffffffffu, p, o);
            if ((t & 31) == 0) spart[t >> 5] = p;
            __syncthreads();
            if (t == 0) {
                float s = b2;
                #pragma unroll
                for (int i = 0; i < 8; i++) s += spart[i];
                if (base + r < N) g_att[base + r] = 1.f / (1.f + expf(-s));
            }
            __syncthreads();
        }
    }
}

// ---------------- K6: fused GEMM -> out_pre (in d_out), bnf stats ----------------
__global__ __launch_bounds__(256) void k_fuse(const float* __restrict__ fw,
                                              const float* __restrict__ fb,
                                              float* __restrict__ out,
                                              int N) {
    int t = threadIdx.x;
    int j = t >> 1, h = t & 1;
    float w[128];
    const float4* wp = reinterpret_cast<const float4*>(fw + (size_t)j * 256 + h * 128);
    #pragma unroll
    for (int k = 0; k < 32; k++) {
        float4 v = __ldg(wp + k);
        w[4*k] = v.x; w[4*k+1] = v.y; w[4*k+2] = v.z; w[4*k+3] = v.w;
    }
    float bias = __ldg(fb + j);
    __shared__ float sc[4][256];
    __shared__ float sa[4];
    float ssum = 0.f, ssq = 0.f;
    int row0 = blockIdx.x * 64;
    for (int rt = 0; rt < 64; rt += 4) {
        int base = row0 + rt;
        if (t < 4) sa[t] = (base + t < N) ? g_att[base + t] : 0.f;
        __syncthreads();
        #pragma unroll
        for (int it = 0; it < 4; it++) {
            int lin = t + it * 256;
            int r = lin >> 8, c = lin & 255;
            float v = 0.f;
            if (base + r < N) {
                float a = sa[r];
                v = (c < 128) ? g_vfeat[(size_t)(base + r) * 128 + c] * a
                              : g_ifeat[(size_t)(base + r) * 128 + (c - 128)] * (1.f - a);
            }
            sc[r][c] = v;
        }
        __syncthreads();
        for (int r = 0; r < 4; r++) {
            if (base + r < N) {
                float a0 = 0.f, a1 = 0.f, a2 = 0.f, a3 = 0.f;
                const float4* xp = reinterpret_cast<const float4*>(&sc[r][0] + h * 128);
                #pragma unroll
                for (int k = 0; k < 32; k++) {
                    float4 xv = xp[k];
                    a0 = fmaf(w[4*k],   xv.x, a0);
                    a1 = fmaf(w[4*k+1], xv.y, a1);
                    a2 = fmaf(w[4*k+2], xv.z, a2);
                    a3 = fmaf(w[4*k+3], xv.w, a3);
                }
                float acc = (a0 + a1) + (a2 + a3);
                acc += __shfl_xor_sync(0xffffffffu, acc, 1);
                if (h == 0) {
                    float o = acc + bias;
                    out[(size_t)(base + r) * 128 + j] = o;
                    ssum += o; ssq += o * o;
                }
            }
        }
        __syncthreads();
    }
    if (h == 0) {
        atomicAdd(&g_stats[256 + j], ssum);
        atomicAdd(&g_stats[384 + j], ssq);
    }
}

// ---------------- K8: in-place final bn + relu on d_out ----------------
__global__ void k_bnrelu(float* __restrict__ out, long total4) {
    long i = (long)blockIdx.x * blockDim.x + threadIdx.x;
    if (i < total4) {
        int cb = (int)((i & 31) * 4);
        float4 v = reinterpret_cast<float4*>(out)[i];
        v.x = fmaxf(fmaf(v.x, g_bnp[256 + cb],     g_bnp[384 + cb]),     0.f);
        v.y = fmaxf(fmaf(v.y, g_bnp[256 + cb + 1], g_bnp[384 + cb + 1]), 0.f);
        v.z = fmaxf(fmaf(v.z, g_bnp[256 + cb + 2], g_bnp[384 + cb + 2]), 0.f);
        v.w = fmaxf(fmaf(v.w, g_bnp[256 + cb + 3], g_bnp[384 + cb + 3]), 0.f);
        reinterpret_cast<float4*>(out)[i] = v;
    }
}

// ---------------- launch ----------------
extern "C" void kernel_launch(void* const* d_in, const int* in_sizes, int n_in,
                              void* d_out, int out_size) {
    const float* vf     = (const float*)d_in[0];
    const int*   coords = (const int*)  d_in[1];
    const float* img    = (const float*)d_in[2];
    const float* P2     = (const float*)d_in[3];
    const float* vt_w1  = (const float*)d_in[4];
    const float* vt_b1  = (const float*)d_in[5];
    const float* bn1_g  = (const float*)d_in[6];
    const float* bn1_b  = (const float*)d_in[7];
    const float* vt_w2  = (const float*)d_in[8];
    const float* vt_b2  = (const float*)d_in[9];
    const float* att_w1 = (const float*)d_in[10];
    const float* att_b1 = (const float*)d_in[11];
    const float* att_w2 = (const float*)d_in[12];
    const float* att_b2 = (const float*)d_in[13];
    const float* fus_w  = (const float*)d_in[14];
    const float* fus_b  = (const float*)d_in[15];
    const float* bnf_g  = (const float*)d_in[16];
    const float* bnf_b  = (const float*)d_in[17];

    int N = in_sizes[1] / 4;   // voxel_coords is [N,4]
    float* out = (float*)d_out;

    k_transpose<<<dim3((W_ + 31) / 32, C2D / 32, B_ * H_), dim3(32, 8)>>>(img);
    k_zero<<<1, 512>>>();
    k_gemm1<<<(N + 127) / 128, 128>>>(vf, vt_w1, vt_b1, N);
    k_fin<<<1, 128>>>(0, bn1_g, bn1_b, N);
    k_gemm2<<<(N + 127) / 128, 128>>>(vt_w2, vt_b2, N);
    k_sample<<<(N + 63) / 64, 128>>>(coords, P2, N);
    k_att<<<(N + 63) / 64, 256>>>(att_w1, att_b1, att_w2, att_b2, N);
    k_fuse<<<(N + 63) / 64, 256>>>(fus_w, fus_b, out, N);
    k_fin<<<1, 128>>>(1, bnf_g, bnf_b, N);
    long total4 = (long)N * 32;
    k_bnrelu<<<(unsigned)((total4 + 255) / 256), 256>>>(out, total4);
}

// round 2
// speedup vs baseline: 1.2953x; 1.2953x over previous
#include <cuda_runtime.h>
#include <math.h>
#include <stdint.h>

// ---------------- problem constants ----------------
#define NMAX 200000
#define B_   4
#define C2D  128
#define H_   96
#define W_   312
#define MID  128
#define C3D  64
#define ROWS_BLK 256

typedef unsigned long long ull;

// packed fp32x2 FMA (sm_103a FFMA2) — ptxas never emits this from C++
__device__ __forceinline__ void fma2(ull& d, ull a, ull b) {
    asm("fma.rn.f32x2 %0, %1, %2, %0;" : "+l"(d) : "l"(a), "l"(b));
}
__device__ __forceinline__ float upsum(ull a) {
    float lo, hi;
    asm("mov.b64 {%0,%1}, %2;" : "=f"(lo), "=f"(hi) : "l"(a));
    return lo + hi;
}

// ---------------- scratch (__device__ globals; no runtime alloc) ----------------
__device__ __align__(16) float g_imgT[(size_t)B_ * H_ * W_ * C2D];
__device__ __align__(16) float g_hpre[(size_t)NMAX * MID];
__device__ __align__(16) float g_vfeat[(size_t)NMAX * MID];
__device__ __align__(16) float g_ifeat[(size_t)NMAX * C2D];
__device__ float g_att[NMAX];
__device__ float g_stats[512];   // [sum1 | sq1 | sumf | sqf]
__device__ float g_bnp[512];     // [scale1 | shift1 | scalef | shiftf]

// ---------------- clear stats ----------------
__global__ void k_zero() {
    if (threadIdx.x < 512) g_stats[threadIdx.x] = 0.f;
}

// ---------------- K0: image transpose [B,C,H,W] -> [B,H,W,C] ----------------
__global__ void k_transpose(const float* __restrict__ img) {
    __shared__ float tile[32][33];
    int bh = blockIdx.z;
    int b  = bh / H_;
    int hh = bh % H_;
    int w0 = blockIdx.x * 32;
    int c0 = blockIdx.y * 32;
    int tx = threadIdx.x, ty = threadIdx.y;
    #pragma unroll
    for (int i = 0; i < 32; i += 8) {
        int c = c0 + ty + i;
        int w = w0 + tx;
        float v = 0.f;
        if (w < W_) v = img[((size_t)(b * C2D + c) * H_ + hh) * W_ + w];
        tile[ty + i][tx] = v;
    }
    __syncthreads();
    #pragma unroll
    for (int i = 0; i < 32; i += 8) {
        int w = w0 + ty + i;
        int c = c0 + tx;
        if (w < W_)
            g_imgT[((size_t)bh * W_ + w) * C2D + c] = tile[tx][ty + i];
    }
}

// ---------------- K1: hpre = vf @ w1^T + b1, bn1 stats ----------------
__global__ __launch_bounds__(128) void k_gemm1(const float* __restrict__ vf,
                                               const float* __restrict__ w1,
                                               const float* __restrict__ b1,
                                               int N) {
    int j = threadIdx.x;
    ull w[32];
    const ulonglong2* wp = reinterpret_cast<const ulonglong2*>(w1 + (size_t)j * C3D);
    #pragma unroll
    for (int k = 0; k < 16; k++) { ulonglong2 v = wp[k]; w[2*k] = v.x; w[2*k+1] = v.y; }
    float bias = __ldg(b1 + j);
    __shared__ __align__(16) float sx[8][C3D];
    float ssum = 0.f, ssq = 0.f;
    int row0 = blockIdx.x * ROWS_BLK;
    for (int rt = 0; rt < ROWS_BLK; rt += 8) {
        int base = row0 + rt;
        if (base >= N) break;
        {   // 8 rows x 64 floats = 128 float4 loads
            int r = j >> 4, c4 = (j & 15) * 4;
            float4 v = make_float4(0.f, 0.f, 0.f, 0.f);
            if (base + r < N)
                v = *reinterpret_cast<const float4*>(vf + (size_t)(base + r) * C3D + c4);
            *reinterpret_cast<float4*>(&sx[r][c4]) = v;
        }
        __syncthreads();
        #pragma unroll
        for (int r = 0; r < 8; r++) {
            ull a0 = 0, a1 = 0, a2 = 0, a3 = 0;
            const ulonglong2* xp = reinterpret_cast<const ulonglong2*>(&sx[r][0]);
            #pragma unroll
            for (int k = 0; k < 8; k++) {
                ulonglong2 x0 = xp[2*k], x1 = xp[2*k+1];
                fma2(a0, w[4*k],   x0.x);
                fma2(a1, w[4*k+1], x0.y);
                fma2(a2, w[4*k+2], x1.x);
                fma2(a3, w[4*k+3], x1.y);
            }
            float acc = bias + ((upsum(a0) + upsum(a1)) + (upsum(a2) + upsum(a3)));
            if (base + r < N) {
                g_hpre[(size_t)(base + r) * MID + j] = acc;
                ssum += acc; ssq += acc * acc;
            }
        }
        __syncthreads();
    }
    atomicAdd(&g_stats[j], ssum);
    atomicAdd(&g_stats[128 + j], ssq);
}

// ---------------- finalize bn stats -> scale/shift ----------------
__global__ void k_fin(int which, const float* __restrict__ g,
                      const float* __restrict__ b, int N) {
    int j = threadIdx.x;
    int o = which * 256;
    float invN = 1.f / (float)N;
    float m   = g_stats[o + j] * invN;
    float msq = g_stats[o + 128 + j] * invN;
    float var = msq - m * m;
    float s = __ldg(g + j) * rsqrtf(var + 1e-5f);
    g_bnp[o + j] = s;
    g_bnp[o + 128 + j] = __ldg(b + j) - m * s;
}

// ---------------- K3: vfeat = relu(bn(hpre)) @ w2^T + b2 ----------------
__global__ __launch_bounds__(128) void k_gemm2(const float* __restrict__ w2,
                                               const float* __restrict__ b2,
                                               int N) {
    int j = threadIdx.x;
    ull w[64];
    const ulonglong2* wp = reinterpret_cast<const ulonglong2*>(w2 + (size_t)j * MID);
    #pragma unroll
    for (int k = 0; k < 32; k++) { ulonglong2 v = wp[k]; w[2*k] = v.x; w[2*k+1] = v.y; }
    float bias = __ldg(b2 + j);
    // per-thread bn params for its fixed load columns c4..c4+3
    int c4 = (j & 31) * 4;
    float s0 = g_bnp[c4],       s1 = g_bnp[c4+1],       s2 = g_bnp[c4+2],       s3 = g_bnp[c4+3];
    float h0 = g_bnp[128+c4],   h1 = g_bnp[128+c4+1],   h2 = g_bnp[128+c4+2],   h3 = g_bnp[128+c4+3];
    __shared__ __align__(16) float sx[8][MID];
    int row0 = blockIdx.x * ROWS_BLK;
    for (int rt = 0; rt < ROWS_BLK; rt += 8) {
        int base = row0 + rt;
        if (base >= N) break;
        #pragma unroll
        for (int it = 0; it < 2; it++) {    // 8 rows x 128 = 256 float4
            int idx = it * 128 + j;
            int r = idx >> 5;
            float4 v = make_float4(0.f, 0.f, 0.f, 0.f);
            if (base + r < N)
                v = *reinterpret_cast<const float4*>(g_hpre + (size_t)(base + r) * MID + c4);
            v.x = fmaxf(fmaf(v.x, s0, h0), 0.f);
            v.y = fmaxf(fmaf(v.y, s1, h1), 0.f);
            v.z = fmaxf(fmaf(v.z, s2, h2), 0.f);
            v.w = fmaxf(fmaf(v.w, s3, h3), 0.f);
            *reinterpret_cast<float4*>(&sx[r][c4]) = v;
        }
        __syncthreads();
        #pragma unroll
        for (int r = 0; r < 8; r++) {
            if (base + r < N) {
                ull a0 = 0, a1 = 0, a2 = 0, a3 = 0;
                const ulonglong2* xp = reinterpret_cast<const ulonglong2*>(&sx[r][0]);
                #pragma unroll
                for (int k = 0; k < 16; k++) {
                    ulonglong2 x0 = xp[2*k], x1 = xp[2*k+1];
                    fma2(a0, w[4*k],   x0.x);
                    fma2(a1, w[4*k+1], x0.y);
                    fma2(a2, w[4*k+2], x1.x);
                    fma2(a3, w[4*k+3], x1.y);
                }
                g_vfeat[(size_t)(base + r) * MID + j] =
                    bias + ((upsum(a0) + upsum(a1)) + (upsum(a2) + upsum(a3)));
            }
        }
        __syncthreads();
    }
}

// ---------------- K4: projection + bilinear gather -> ifeat ----------------
__global__ __launch_bounds__(128) void k_sample(const int* __restrict__ coords,
                                                const float* __restrict__ P2,
                                                int N) {
    int j = threadIdx.x;
    int row0 = blockIdx.x * 64;
    int rend = N - row0; if (rend > 64) rend = 64;
    for (int r = 0; r < rend; r++) {
        int row = row0 + r;
        int4 c4 = __ldg(reinterpret_cast<const int4*>(coords + (size_t)row * 4));
        int b = c4.x;
        float p0 = (float)c4.y * 0.05f;
        float p1 = (float)c4.z * 0.05f - 40.f;
        float p2 = (float)c4.w * 0.1f  - 3.f;
        const float* P = P2 + b * 12;
        float cam0 = __ldg(P+0)*p0 + __ldg(P+1)*p1 + __ldg(P+2)*p2  + __ldg(P+3);
        float cam1 = __ldg(P+4)*p0 + __ldg(P+5)*p1 + __ldg(P+6)*p2  + __ldg(P+7);
        float cam2 = __ldg(P+8)*p0 + __ldg(P+9)*p1 + __ldg(P+10)*p2 + __ldg(P+11);
        float d = cam2 + 1e-8f;
        float u = cam0 / d;
        float v = cam1 / d;
        float gx = u / (float)W_ * 2.f - 1.f; gx = fminf(fmaxf(gx, -1.f), 1.f);
        float gy = v / (float)H_ * 2.f - 1.f; gy = fminf(fmaxf(gy, -1.f), 1.f);
        float ix = ((gx + 1.f) * (float)W_ - 1.f) * 0.5f;
        float iy = ((gy + 1.f) * (float)H_ - 1.f) * 0.5f;
        float x0f = floorf(ix), y0f = floorf(iy);
        float wx = ix - x0f, wy = iy - y0f;
        int x0 = (int)x0f, y0 = (int)y0f;
        float acc = 0.f;
        #pragma unroll
        for (int cy = 0; cy < 2; cy++) {
            #pragma unroll
            for (int cx = 0; cx < 2; cx++) {
                int yc = y0 + cy, xc = x0 + cx;
                float wgt = (cx ? wx : 1.f - wx) * (cy ? wy : 1.f - wy);
                if (xc >= 0 && xc < W_ && yc >= 0 && yc < H_) {
                    acc = fmaf(wgt,
                               g_imgT[(((size_t)(b * H_ + yc)) * W_ + xc) * C2D + j],
                               acc);
                }
            }
        }
        g_ifeat[(size_t)row * C2D + j] = acc;
    }
}

// ---------------- K5: attention scalar a per row ----------------
__global__ __launch_bounds__(256) void k_att(const float* __restrict__ aw1,
                                             const float* __restrict__ ab1,
                                             const float* __restrict__ aw2,
                                             const float* __restrict__ ab2,
                                             int N) {
    int t = threadIdx.x;
    int j = t >> 1, h = t & 1;
    ull w[64];
    const ulonglong2* wp = reinterpret_cast<const ulonglong2*>(aw1 + (size_t)j * 256 + h * 128);
    #pragma unroll
    for (int k = 0; k < 32; k++) { ulonglong2 v = wp[k]; w[2*k] = v.x; w[2*k+1] = v.y; }
    float bj  = __ldg(ab1 + j);
    float w2j = (h == 0) ? __ldg(aw2 + j) : 0.f;   // zero h==1 duplicates
    float b2  = __ldg(ab2);
    __shared__ __align__(16) float sc[8][256];
    __shared__ float srow[8];
    int row0 = blockIdx.x * ROWS_BLK;
    for (int rt = 0; rt < ROWS_BLK; rt += 8) {
        int base = row0 + rt;
        if (base >= N) break;
        if (t < 8) srow[t] = b2;
        __syncthreads();
        #pragma unroll
        for (int it = 0; it < 2; it++) {   // 8 rows x 256 = 512 float4
            int idx = it * 256 + t;
            int r = idx >> 6;
            int c4 = (idx & 63) * 4;
            float4 v = make_float4(0.f, 0.f, 0.f, 0.f);
            if (base + r < N) {
                if (c4 < 128)
                    v = *reinterpret_cast<const float4*>(g_vfeat + (size_t)(base + r) * 128 + c4);
                else
                    v = *reinterpret_cast<const float4*>(g_ifeat + (size_t)(base + r) * 128 + c4 - 128);
            }
            *reinterpret_cast<float4*>(&sc[r][c4]) = v;
        }
        __syncthreads();
        float p[8];
        #pragma unroll
        for (int r = 0; r < 8; r++) {
            ull a0 = 0, a1 = 0, a2 = 0, a3 = 0;
            const ulonglong2* xp = reinterpret_cast<const ulonglong2*>(&sc[r][0] + h * 128);
            #pragma unroll
            for (int k = 0; k < 16; k++) {
                ulonglong2 x0 = xp[2*k], x1 = xp[2*k+1];
                fma2(a0, w[4*k],   x0.x);
                fma2(a1, w[4*k+1], x0.y);
                fma2(a2, w[4*k+2], x1.x);
                fma2(a3, w[4*k+3], x1.y);
            }
            float s = (upsum(a0) + upsum(a1)) + (upsum(a2) + upsum(a3));
            s += __shfl_xor_sync(0xffffffffu, s, 1);   // combine halves
            p[r] = fmaxf(s + bj, 0.f) * w2j;
        }
        #pragma unroll
        for (int r = 0; r < 8; r++) {
            float v = p[r];
            #pragma unroll
            for (int o = 16; o > 0; o >>= 1) v += __shfl_xor_sync(0xffffffffu, v, o);
            if ((t & 31) == 0) atomicAdd(&srow[r], v);
        }
        __syncthreads();
        if (t < 8 && base + t < N)
            g_att[base + t] = 1.f / (1.f + expf(-srow[t]));
        __syncthreads();
    }
}

// ---------------- K6: fused GEMM -> out_pre (in d_out), bnf stats ----------------
__global__ __launch_bounds__(256) void k_fuse(const float* __restrict__ fw,
                                              const float* __restrict__ fb,
                                              float* __restrict__ out,
                                              int N) {
    int t = threadIdx.x;
    int j = t >> 1, h = t & 1;
    ull w[64];
    const ulonglong2* wp = reinterpret_cast<const ulonglong2*>(fw + (size_t)j * 256 + h * 128);
    #pragma unroll
    for (int k = 0; k < 32; k++) { ulonglong2 v = wp[k]; w[2*k] = v.x; w[2*k+1] = v.y; }
    float bias = __ldg(fb + j);
    __shared__ __align__(16) float sc[8][256];
    __shared__ float sa[8];
    float ssum = 0.f, ssq = 0.f;
    int row0 = blockIdx.x * ROWS_BLK;
    for (int rt = 0; rt < ROWS_BLK; rt += 8) {
        int base = row0 + rt;
        if (base >= N) break;
        if (t < 8) sa[t] = (base + t < N) ? g_att[base + t] : 0.f;
        __syncthreads();
        #pragma unroll
        for (int it = 0; it < 2; it++) {
            int idx = it * 256 + t;
            int r = idx >> 6;
            int c4 = (idx & 63) * 4;
            float4 v = make_float4(0.f, 0.f, 0.f, 0.f);
            if (base + r < N) {
                float a = sa[r];
                if (c4 < 128) {
                    v = *reinterpret_cast<const float4*>(g_vfeat + (size_t)(base + r) * 128 + c4);
                    v.x *= a; v.y *= a; v.z *= a; v.w *= a;
                } else {
                    v = *reinterpret_cast<const float4*>(g_ifeat + (size_t)(base + r) * 128 + c4 - 128);
                    float ia = 1.f - a;
                    v.x *= ia; v.y *= ia; v.z *= ia; v.w *= ia;
                }
            }
            *reinterpret_cast<float4*>(&sc[r][c4]) = v;
        }
        __syncthreads();
        #pragma unroll
        for (int r = 0; r < 8; r++) {
            if (base + r < N) {
                ull a0 = 0, a1 = 0, a2 = 0, a3 = 0;
                const ulonglong2* xp = reinterpret_cast<const ulonglong2*>(&sc[r][0] + h * 128);
                #pragma unroll
                for (int k = 0; k < 16; k++) {
                    ulonglong2 x0 = xp[2*k], x1 = xp[2*k+1];
                    fma2(a0, w[4*k],   x0.x);
                    fma2(a1, w[4*k+1], x0.y);
                    fma2(a2, w[4*k+2], x1.x);
                    fma2(a3, w[4*k+3], x1.y);
                }
                float acc = (upsum(a0) + upsum(a1)) + (upsum(a2) + upsum(a3));
                acc += __shfl_xor_sync(0xffffffffu, acc, 1);
                if (h == 0) {
                    float o = acc + bias;
                    out[(size_t)(base + r) * 128 + j] = o;
                    ssum += o; ssq += o * o;
                }
            }
        }
        __syncthreads();
    }
    if (h == 0) {
        atomicAdd(&g_stats[256 + j], ssum);
        atomicAdd(&g_stats[384 + j], ssq);
    }
}

// ---------------- K8: in-place final bn + relu on d_out ----------------
__global__ void k_bnrelu(float* __restrict__ out, long total4) {
    long i = (long)blockIdx.x * blockDim.x + threadIdx.x;
    if (i < total4) {
        int cb = (int)((i & 31) * 4);
        float4 v = reinterpret_cast<float4*>(out)[i];
        v.x = fmaxf(fmaf(v.x, g_bnp[256 + cb],     g_bnp[384 + cb]),     0.f);
        v.y = fmaxf(fmaf(v.y, g_bnp[256 + cb + 1], g_bnp[384 + cb + 1]), 0.f);
        v.z = fmaxf(fmaf(v.z, g_bnp[256 + cb + 2], g_bnp[384 + cb + 2]), 0.f);
        v.w = fmaxf(fmaf(v.w, g_bnp[256 + cb + 3], g_bnp[384 + cb + 3]), 0.f);
        reinterpret_cast<float4*>(out)[i] = v;
    }
}

// ---------------- launch ----------------
extern "C" void kernel_launch(void* const* d_in, const int* in_sizes, int n_in,
                              void* d_out, int out_size) {
    const float* vf     = (const float*)d_in[0];
    const int*   coords = (const int*)  d_in[1];
    const float* img    = (const float*)d_in[2];
    const float* P2     = (const float*)d_in[3];
    const float* vt_w1  = (const float*)d_in[4];
    const float* vt_b1  = (const float*)d_in[5];
    const float* bn1_g  = (const float*)d_in[6];
    const float* bn1_b  = (const float*)d_in[7];
    const float* vt_w2  = (const float*)d_in[8];
    const float* vt_b2  = (const float*)d_in[9];
    const float* att_w1 = (const float*)d_in[10];
    const float* att_b1 = (const float*)d_in[11];
    const float* att_w2 = (const float*)d_in[12];
    const float* att_b2 = (const float*)d_in[13];
    const float* fus_w  = (const float*)d_in[14];
    const float* fus_b  = (const float*)d_in[15];
    const float* bnf_g  = (const float*)d_in[16];
    const float* bnf_b  = (const float*)d_in[17];

    int N = in_sizes[1] / 4;
    float* out = (float*)d_out;
    int nblk = (N + ROWS_BLK - 1) / ROWS_BLK;

    k_transpose<<<dim3((W_ + 31) / 32, C2D / 32, B_ * H_), dim3(32, 8)>>>(img);
    k_zero<<<1, 512>>>();
    k_gemm1<<<nblk, 128>>>(vf, vt_w1, vt_b1, N);
    k_fin<<<1, 128>>>(0, bn1_g, bn1_b, N);
    k_gemm2<<<nblk, 128>>>(vt_w2, vt_b2, N);
    k_sample<<<(N + 63) / 64, 128>>>(coords, P2, N);
    k_att<<<nblk, 256>>>(att_w1, att_b1, att_w2, att_b2, N);
    k_fuse<<<nblk, 256>>>(fus_w, fus_b, out, N);
    k_fin<<<1, 128>>>(1, bnf_g, bnf_b, N);
    long total4 = (long)N * 32;
    k_bnrelu<<<(unsigned)((total4 + 255) / 256), 256>>>(out, total4);
}